// round 16
// baseline (speedup 1.0000x reference)
#include <cuda_runtime.h>
#include <cuda.h>
#include <cuda_bf16.h>
#include <cstdint>

#define B_   24
#define NA_  50
#define T_   10
#define NV_  196
#define D_   512
#define M_   (B_*NA_)        // 1200
#define N_   (B_*T_*NV_)     // 47040
#define G_   (B_*T_)         // 240

#define BN_    192           // CTA tile N (192*245 = 47040 exact)
#define NTM    10            // ceil(1200/128)
#define NTN    245
#define NTILES (NTM*NTN)     // 2450
#define NCW    12            // consumer warps
#define NSUMSQ (NTILES*NCW)  // 29400
#define KCH    8             // 512/64 k-chunks per tile
#define GRID_  148
#define NSTAGE 4

#define A_BYTES     16384    // 128 rows x 64 bf16 (128B rows)
#define V_BYTES     24576    // 192 rows x 64 bf16
#define STAGE_BYTES (A_BYTES + V_BYTES)       // 40960
#define SMEM_TOTAL  (NSTAGE*STAGE_BYTES)      // 163840

// ---------------- device scratch (normalized RNE bf16) ----------------
__device__ __align__(128) __nv_bfloat16 g_A[M_*D_];            // 1.2 MB
__device__ __align__(128) __nv_bfloat16 g_V[(size_t)N_*D_];    // 48 MB
__device__ unsigned int  g_maxvis[M_*G_];
__device__ float         g_sumsq[NSUMSQ];
__device__ int           g_fraccnt;

// ---------------- PTX helpers (all non-'a' features) ----------------
__device__ __forceinline__ uint32_t smem_u32(const void* p) {
    uint32_t a;
    asm("{ .reg .u64 t; cvta.to.shared.u64 t, %1; cvt.u32.u64 %0, t; }" : "=r"(a) : "l"(p));
    return a;
}
#define MBARRIER_INIT(a, c) \
    asm volatile("mbarrier.init.shared.b64 [%0], %1;" :: "r"((uint32_t)(a)), "r"((uint32_t)(c)) : "memory")
#define MBARRIER_ARRIVE(a) \
    asm volatile("mbarrier.arrive.shared.b64 _, [%0];" :: "r"((uint32_t)(a)) : "memory")
#define MBARRIER_EXPECT_TX(a, b) \
    asm volatile("mbarrier.arrive.expect_tx.shared.b64 _, [%0], %1;" :: "r"((uint32_t)(a)), "r"((uint32_t)(b)) : "memory")
#define MBARRIER_WAIT_PARITY(a, ph) do { \
    uint32_t _m = (uint32_t)(a); uint32_t _p = (uint32_t)(ph); uint32_t _d; \
    asm volatile("{\n\t.reg .pred p;\n\t" \
        "mbarrier.try_wait.parity.acquire.cta.shared::cta.b64 p, [%1], %2;\n\t" \
        "selp.b32 %0, 1, 0, p;\n\t}" : "=r"(_d) : "r"(_m), "r"(_p) : "memory"); \
    if (!_d) { \
        asm volatile("{\n\t.reg .pred P1;\n\tWL_%=:\n\t" \
            "mbarrier.try_wait.parity.acquire.cta.shared::cta.b64 P1, [%0], %1, 0x989680;\n\t" \
            "@P1 bra.uni WD_%=;\n\tbra.uni WL_%=;\n\tWD_%=:\n\t}" \
            :: "r"(_m), "r"(_p) : "memory"); \
    } } while (0)
#define FENCE_PROXY_ASYNC() asm volatile("fence.proxy.async.shared::cta;" ::: "memory")

__device__ __forceinline__ void tma_ld_2d(uint32_t dst, const CUtensorMap* map,
                                          int cx, int cy, uint32_t mbar) {
    asm volatile(
        "cp.async.bulk.tensor.2d.shared::cta.global.tile.mbarrier::complete_tx::bytes "
        "[%0], [%1, {%2, %3}], [%4];"
        :: "r"(dst), "l"(map), "r"(cx), "r"(cy), "r"(mbar) : "memory");
}
__device__ __forceinline__ void ldsm4(uint32_t r[4], uint32_t addr) {
    asm volatile("ldmatrix.sync.aligned.m8n8.x4.shared.b16 {%0,%1,%2,%3}, [%4];"
        : "=r"(r[0]), "=r"(r[1]), "=r"(r[2]), "=r"(r[3]) : "r"(addr));
}
__device__ __forceinline__ void mma_bf16(float d[4], const uint32_t a[4], const uint32_t b[2]) {
    asm volatile("mma.sync.aligned.m16n8k16.row.col.f32.bf16.bf16.f32 "
        "{%0,%1,%2,%3}, {%4,%5,%6,%7}, {%8,%9}, {%0,%1,%2,%3};"
        : "+f"(d[0]), "+f"(d[1]), "+f"(d[2]), "+f"(d[3])
        : "r"(a[0]), "r"(a[1]), "r"(a[2]), "r"(a[3]), "r"(b[0]), "r"(b[1]));
}

// monotone float<->uint encoding for atomicMax over signed floats
__device__ __forceinline__ unsigned int encf(float f) {
    unsigned int u = __float_as_uint(f);
    return (u & 0x80000000u) ? ~u : (u | 0x80000000u);
}
__device__ __forceinline__ float decf(unsigned int e) {
    unsigned int u = (e & 0x80000000u) ? (e & 0x7fffffffu) : ~e;
    return __uint_as_float(u);
}

// ---- kernel 1: fused init + L2-normalize + RNE bf16 convert ----------------
#define PREP_BLOCKS (M_ + N_)
#define MV_PER_BLK  ((M_*G_ + PREP_BLOCKS - 1) / PREP_BLOCKS)   // 6
__global__ void prep_kernel(const float* __restrict__ audio,
                            const float* __restrict__ visual) {
    const int blk = blockIdx.x;
    {
        int base = blk * MV_PER_BLK;
        for (int j = threadIdx.x; j < MV_PER_BLK; j += 128) {
            int i = base + j;
            if (i < M_ * G_) g_maxvis[i] = 0u;
        }
        if (blk == 0 && threadIdx.x == 0) g_fraccnt = 0;
    }
    const int which = (blk >= M_);
    const float* in = which ? visual : audio;
    __nv_bfloat16* out = which ? g_V : g_A;
    const size_t row = which ? (size_t)(blk - M_) : (size_t)blk;

    float4 v = reinterpret_cast<const float4*>(in + row * D_)[threadIdx.x];
    float s = v.x * v.x + v.y * v.y + v.z * v.z + v.w * v.w;
#pragma unroll
    for (int o = 16; o; o >>= 1) s += __shfl_xor_sync(0xffffffffu, s, o);
    __shared__ float ws[4];
    __shared__ float sinv;
    if ((threadIdx.x & 31) == 0) ws[threadIdx.x >> 5] = s;
    __syncthreads();
    if (threadIdx.x == 0) sinv = 1.0f / fmaxf(sqrtf(ws[0] + ws[1] + ws[2] + ws[3]), 1e-12f);
    __syncthreads();
    float iv = sinv;
    __nv_bfloat162 h01 = __float22bfloat162_rn(make_float2(v.x * iv, v.y * iv));
    __nv_bfloat162 h23 = __float22bfloat162_rn(make_float2(v.z * iv, v.w * iv));
    uint2 hu;
    hu.x = *reinterpret_cast<uint32_t*>(&h01);
    hu.y = *reinterpret_cast<uint32_t*>(&h23);
    *reinterpret_cast<uint2*>(out + row * D_ + threadIdx.x * 4) = hu;
}

// ------- kernel 2: persistent bf16 GEMM (round-14 exact) ---------------------
__global__ __launch_bounds__(416, 1)
void gemm_mma(const __grid_constant__ CUtensorMap tmA,
              const __grid_constant__ CUtensorMap tmV,
              const float* __restrict__ tempP) {
    extern __shared__ __align__(1024) char dsmem[];
    __shared__ uint64_t s_full[NSTAGE], s_empty[NSTAGE];

    const int tid   = threadIdx.x;
    const int lane  = tid & 31;
    const int wid   = tid >> 5;
    const uint32_t sbase = smem_u32(dsmem);
    uint32_t FULL[NSTAGE], EMPTY[NSTAGE];
#pragma unroll
    for (int i = 0; i < NSTAGE; i++) {
        FULL[i]  = smem_u32(&s_full[i]);
        EMPTY[i] = smem_u32(&s_empty[i]);
    }

    if (tid == 0) {
#pragma unroll
        for (int i = 0; i < NSTAGE; i++) {
            MBARRIER_INIT(FULL[i], 1);
            MBARRIER_INIT(EMPTY[i], NCW);
        }
        FENCE_PROXY_ASYNC();
    }
    __syncthreads();

    const int bx = blockIdx.x;
    const int ntiles = (bx < NTILES) ? ((NTILES - 1 - bx) / GRID_ + 1) : 0;
    const int totChunks = ntiles * KCH;

    // ================= producer warp (single thread) =================
    if (tid == 384) {
        for (int gc = 0; gc < totChunks; gc++) {
            const int st = gc % NSTAGE;
            const int n  = gc / NSTAGE;
            if (n >= 1) MBARRIER_WAIT_PARITY(EMPTY[st], (n - 1) & 1);
            const int s   = bx + (gc / KCH) * GRID_;
            const int c   = gc % KCH;
            const int rm0 = (s % NTM) * 128;
            const int cn0 = (s / NTM) * BN_;
            const int k0  = c * 64;
            const uint32_t stg = sbase + st * STAGE_BYTES;
            MBARRIER_EXPECT_TX(FULL[st], STAGE_BYTES);
            tma_ld_2d(stg,           &tmA, k0, rm0, FULL[st]);
            tma_ld_2d(stg + A_BYTES, &tmV, k0, cn0, FULL[st]);
        }
        return;
    }
    if (tid > 384) return;

    // ================= consumer warps (0..11) =================
    const int warpM = wid & 3;        // 4 row groups of 32
    const int warpN = wid >> 2;       // 3 col groups of 64
    const float invT = 1.0f / __ldg(tempP);

    const uint32_t laneHi = (lane & 16);
    uint32_t offA[2][4], offB[4][4];
#pragma unroll
    for (int mt = 0; mt < 2; mt++) {
        int r = warpM * 32 + mt * 16 + (lane & 15);
        uint32_t sw = (r & 7) << 4;
#pragma unroll
        for (int ks = 0; ks < 4; ks++)
            offA[mt][ks] = (uint32_t)(r * 128) + ((ks * 32 + laneHi) ^ sw);
    }
#pragma unroll
    for (int p = 0; p < 4; p++) {
        int r = warpN * 64 + p * 16 + (lane & 15);
        uint32_t sw = (r & 7) << 4;
#pragma unroll
        for (int ks = 0; ks < 4; ks++)
            offB[p][ks] = (uint32_t)(r * 128) + ((ks * 32 + laneHi) ^ sw);
    }

    int gc = 0;
    for (int s = bx; s < NTILES; s += GRID_) {
        const int rm0 = (s % NTM) * 128;
        const int cn0 = (s / NTM) * BN_;

        float acc[2][8][4];
#pragma unroll
        for (int mt = 0; mt < 2; mt++)
#pragma unroll
            for (int nt = 0; nt < 8; nt++)
#pragma unroll
                for (int e = 0; e < 4; e++) acc[mt][nt][e] = 0.f;

        for (int c = 0; c < KCH; c++, gc++) {
            const int st = gc % NSTAGE;
            MBARRIER_WAIT_PARITY(FULL[st], (gc / NSTAGE) & 1);
            const uint32_t pA = sbase + st * STAGE_BYTES;
            const uint32_t pV = pA + A_BYTES;

#pragma unroll
            for (int ks = 0; ks < 4; ks++) {       // 4 k16 steps per k64 chunk
                uint32_t a[2][4];
                ldsm4(a[0], pA + offA[0][ks]);
                ldsm4(a[1], pA + offA[1][ks]);
                uint32_t bfr[8][2];
#pragma unroll
                for (int p = 0; p < 4; p++) {
                    uint32_t t[4];
                    ldsm4(t, pV + offB[p][ks]);
                    bfr[2*p][0]   = t[0]; bfr[2*p][1]   = t[2];
                    bfr[2*p+1][0] = t[1]; bfr[2*p+1][1] = t[3];
                }
#pragma unroll
                for (int mt = 0; mt < 2; mt++)
#pragma unroll
                    for (int nt = 0; nt < 8; nt++)
                        mma_bf16(acc[mt][nt], a[mt], bfr[nt]);
            }
            if (lane == 0) MBARRIER_ARRIVE(EMPTY[st]);
        }

        // ---- fused epilogue: x invT, segmented max, clamp^2 sum --------------
        const int gB  = cn0 / NV_;
        const int bnd = (gB + 1) * NV_;
        float ssq = 0.f;
#pragma unroll
        for (int mt = 0; mt < 2; mt++) {
            const int row0 = rm0 + warpM * 32 + mt * 16 + (lane >> 2);
            const int row1 = row0 + 8;
            float mx[2][2] = {{-3.0e38f, -3.0e38f}, {-3.0e38f, -3.0e38f}};
#pragma unroll
            for (int nt = 0; nt < 8; nt++) {
                const int c0 = cn0 + warpN * 64 + nt * 8 + (lane & 3) * 2;
#pragma unroll
                for (int e = 0; e < 4; e++) {
                    const int row = (e < 2) ? row0 : row1;
                    float sv = acc[mt][nt][e] * invT;
                    float nn = fmaxf(fminf(sv, 0.f), -20.f);
                    ssq += nn * nn;          // OOB rows: acc==0 (TMA zero-fill) -> 0
                    if (row < M_) {
                        int g = ((c0 + (e & 1)) < bnd) ? 0 : 1;
                        mx[e >> 1][g] = fmaxf(mx[e >> 1][g], sv);
                    }
                }
            }
#pragma unroll
            for (int h = 0; h < 2; h++)
#pragma unroll
                for (int g = 0; g < 2; g++) {
                    float v = mx[h][g];
                    v = fmaxf(v, __shfl_xor_sync(0xffffffffu, v, 1));
                    v = fmaxf(v, __shfl_xor_sync(0xffffffffu, v, 2));
                    mx[h][g] = v;
                }
            if ((lane & 3) == 0) {
                if (row0 < M_) {
                    if (mx[0][0] > -1.0e38f) atomicMax(&g_maxvis[row0 * G_ + gB],     encf(mx[0][0]));
                    if (mx[0][1] > -1.0e38f) atomicMax(&g_maxvis[row0 * G_ + gB + 1], encf(mx[0][1]));
                }
                if (row1 < M_) {
                    if (mx[1][0] > -1.0e38f) atomicMax(&g_maxvis[row1 * G_ + gB],     encf(mx[1][0]));
                    if (mx[1][1] > -1.0e38f) atomicMax(&g_maxvis[row1 * G_ + gB + 1], encf(mx[1][1]));
                }
            }
        }
#pragma unroll
        for (int o = 16; o; o >>= 1) ssq += __shfl_xor_sync(0xffffffffu, ssq, o);
        if (lane == 0) g_sumsq[s * NCW + wid] = ssq;   // per-warp partial
    }
}

// ---- kernel 3: fused temporal aggregation + finalize (single block) ---------
#define NPAIR (B_*B_)   // 576
__global__ __launch_bounds__(1024)
void finalize(float* __restrict__ out,
              const float* __restrict__ tempP,
              const float* __restrict__ sfP,
              const float* __restrict__ thP) {
    const int t = threadIdx.x;
    __shared__ float sh_clip[NPAIR];
    __shared__ float sh_sel[B_];
    __shared__ float la[B_], lv[B_];
    __shared__ float sp[1024];
    __shared__ int   sc[1024];

    const float th = 1.0f / (1.0f + expf(-__ldg(thP)));
    const float sf = __ldg(sfP);

    // ---- phase 1: per-pair temporal aggregation (threads 0..575) ----
    int cnt = 0;
    if (t < NPAIR) {
        const int x = t / B_;
        const int y = t % B_;
        float ts = 0.f, srs = 0.f;
#pragma unroll 5
        for (int a = 0; a < NA_; a++) {
            const int base = (x * NA_ + a) * G_ + y * T_;
            float wsum = 0.f, ws = 0.f;
#pragma unroll
            for (int tt = 0; tt < T_; tt++) {
                float m = decf(g_maxvis[base + tt]);
                float raw = m - th;
                float sel = fmaxf(raw, 0.f) * sf;
                ws += m * sel;
                wsum += sel;
                cnt += (raw > 0.f) ? 1 : 0;
                if (x == y) srs += 0.5f * (tanhf(20.f * raw) + 1.f);
            }
            ts += ws / fmaxf(wsum, 1e-6f);
        }
        sh_clip[t] = ts / (float)NA_;
        if (x == y) sh_sel[x] = srs;
    }
    sc[t] = cnt;

    // ---- phase 1b: sumsq partials (all 1024 threads) ----
    float acc = 0.f;
    for (int i = t; i < NSUMSQ; i += 1024) acc += g_sumsq[i];
    sp[t] = acc;
    __syncthreads();

    // tree reductions (fixed order -> deterministic)
#pragma unroll
    for (int o = 512; o; o >>= 1) {
        if (t < o) { sp[t] += sp[t + o]; sc[t] += sc[t + o]; }
        __syncthreads();
    }

    // ---- phase 2: softmax rows/cols (threads 0..23) ----
    if (t < B_) {
        float m = -3.0e38f;
        for (int j = 0; j < B_; j++) m = fmaxf(m, sh_clip[t * B_ + j]);
        float s = 0.f;
        for (int j = 0; j < B_; j++) s += expf(sh_clip[t * B_ + j] - m);
        la[t] = -(sh_clip[t * B_ + t] - (logf(s) + m));
        float m2 = -3.0e38f;
        for (int j = 0; j < B_; j++) m2 = fmaxf(m2, sh_clip[j * B_ + t]);
        float s2 = 0.f;
        for (int j = 0; j < B_; j++) s2 += expf(sh_clip[j * B_ + t] - m2);
        lv[t] = -(sh_clip[t * B_ + t] - (logf(s2) + m2));
    }
    __syncthreads();

    if (t == 0) {
        float sumsq = sp[0];

        float contr = 0.f;
        for (int i = 0; i < B_; i++) contr += la[i] + lv[i];
        contr = contr / (float)B_ * 0.5f;

        float temp = *tempP;
        float l_nonneg = sumsq / 56448000.0f;
        float lt = logf(temp);
        float tlow = fmaxf(-lt, 0.f);  tlow *= tlow;
        float thigh = fmaxf(lt - logf(4.0f), 0.f); thigh *= thigh;
        float l_cal = tlow + thigh;
        float a1 = fmaxf(th - 0.9f, 0.f), a2 = fmaxf(0.1f - th, 0.f);
        float l_th = a1 * a1 + a2 * a2;
        float b1 = fmaxf(sf - 20.f, 0.f), b2 = fmaxf(1.f - sf, 0.f);
        float l_sc = b1 * b1 + b2 * b2;
        float reg = 0.15f * l_nonneg + 2.0f * l_cal + 0.1f * l_th + 0.1f * l_sc;

        float frac = (float)sc[0] / 288000.0f;

        float selmean = 0.f;
        for (int i = 0; i < B_; i++) selmean += sh_sel[i];
        selmean /= 12000.0f;
        float selrew = -0.1f * log1pf(selmean);

        out[0] = selrew + contr + reg;
        out[1] = contr;
        out[2] = reg;
        out[3] = frac;
        out[4] = selrew;
    }
}

// ---------------- host: tensor maps via driver entry point ----------------
typedef CUresult (*EncTiledFn)(CUtensorMap*, CUtensorMapDataType, cuuint32_t, void*,
                               const cuuint64_t*, const cuuint64_t*, const cuuint32_t*,
                               const cuuint32_t*, CUtensorMapInterleave, CUtensorMapSwizzle,
                               CUtensorMapL2promotion, CUtensorMapFloatOOBfill);

static void make_map(EncTiledFn enc, CUtensorMap* m, void* base,
                     unsigned long long rows, unsigned box1) {
    cuuint64_t dims[2]    = {(cuuint64_t)D_, (cuuint64_t)rows};
    cuuint64_t strides[1] = {(cuuint64_t)(D_ * 2)};
    cuuint32_t box[2]     = {64u, box1};     // 64 bf16 = 128B rows (SW128 atom)
    cuuint32_t es[2]      = {1u, 1u};
    enc(m, CU_TENSOR_MAP_DATA_TYPE_BFLOAT16, 2, base, dims, strides, box, es,
        CU_TENSOR_MAP_INTERLEAVE_NONE, CU_TENSOR_MAP_SWIZZLE_128B,
        CU_TENSOR_MAP_L2_PROMOTION_L2_128B, CU_TENSOR_MAP_FLOAT_OOB_FILL_NONE);
}

extern "C" void kernel_launch(void* const* d_in, const int* in_sizes, int n_in,
                              void* d_out, int out_size) {
    const float* audio  = (const float*)d_in[0];
    const float* visual = (const float*)d_in[1];
    const float* tempP  = (const float*)d_in[2];
    const float* sfP    = (const float*)d_in[3];
    const float* thP    = (const float*)d_in[4];
    float* out = (float*)d_out;

    void* encPtr = nullptr;
    cudaDriverEntryPointQueryResult qres;
    cudaGetDriverEntryPoint("cuTensorMapEncodeTiled", &encPtr, cudaEnableDefault, &qres);
    EncTiledFn enc = (EncTiledFn)encPtr;

    void *pA, *pV;
    cudaGetSymbolAddress(&pA, g_A);
    cudaGetSymbolAddress(&pV, g_V);

    CUtensorMap tmA, tmV;
    make_map(enc, &tmA, pA, M_, 128u);
    make_map(enc, &tmV, pV, N_, 192u);

    cudaFuncSetAttribute(gemm_mma, cudaFuncAttributeMaxDynamicSharedMemorySize, SMEM_TOTAL);

    prep_kernel<<<PREP_BLOCKS, 128>>>(audio, visual);
    gemm_mma<<<GRID_, 416, SMEM_TOTAL>>>(tmA, tmV, tempP);
    finalize<<<1, 1024>>>(out, tempP, sfP, thP);
}

// round 17
// speedup vs baseline: 1.3192x; 1.3192x over previous
#include <cuda_runtime.h>
#include <cuda.h>
#include <cuda_bf16.h>
#include <cstdint>

#define B_   24
#define NA_  50
#define T_   10
#define NV_  196
#define D_   512
#define M_   (B_*NA_)        // 1200
#define N_   (B_*T_*NV_)     // 47040
#define G_   (B_*T_)         // 240

#define BN_    192           // CTA tile N (192*245 = 47040 exact)
#define NTM    10            // ceil(1200/128)
#define NTN    245
#define NTILES (NTM*NTN)     // 2450
#define NCW    12            // consumer warps
#define NSUMSQ (NTILES*NCW)  // 29400
#define KCH    8             // 512/64 k-chunks per tile
#define GRID_  148
#define NSTAGE 4

#define A_BYTES     16384    // 128 rows x 64 bf16 (128B rows)
#define V_BYTES     24576    // 192 rows x 64 bf16
#define STAGE_BYTES (A_BYTES + V_BYTES)       // 40960
#define SMEM_TOTAL  (NSTAGE*STAGE_BYTES)      // 163840

// ---------------- device scratch (normalized RNE bf16) ----------------
__device__ __align__(128) __nv_bfloat16 g_A[M_*D_];            // 1.2 MB
__device__ __align__(128) __nv_bfloat16 g_V[(size_t)N_*D_];    // 48 MB
__device__ unsigned int  g_maxvis[M_*G_];
__device__ float         g_sumsq[NSUMSQ];
__device__ float         g_clip[B_*B_];
__device__ float         g_selsum[B_];
__device__ int           g_fraccnt;

// ---------------- PTX helpers (all non-'a' features) ----------------
__device__ __forceinline__ uint32_t smem_u32(const void* p) {
    uint32_t a;
    asm("{ .reg .u64 t; cvta.to.shared.u64 t, %1; cvt.u32.u64 %0, t; }" : "=r"(a) : "l"(p));
    return a;
}
#define MBARRIER_INIT(a, c) \
    asm volatile("mbarrier.init.shared.b64 [%0], %1;" :: "r"((uint32_t)(a)), "r"((uint32_t)(c)) : "memory")
#define MBARRIER_ARRIVE(a) \
    asm volatile("mbarrier.arrive.shared.b64 _, [%0];" :: "r"((uint32_t)(a)) : "memory")
#define MBARRIER_EXPECT_TX(a, b) \
    asm volatile("mbarrier.arrive.expect_tx.shared.b64 _, [%0], %1;" :: "r"((uint32_t)(a)), "r"((uint32_t)(b)) : "memory")
#define MBARRIER_WAIT_PARITY(a, ph) do { \
    uint32_t _m = (uint32_t)(a); uint32_t _p = (uint32_t)(ph); uint32_t _d; \
    asm volatile("{\n\t.reg .pred p;\n\t" \
        "mbarrier.try_wait.parity.acquire.cta.shared::cta.b64 p, [%1], %2;\n\t" \
        "selp.b32 %0, 1, 0, p;\n\t}" : "=r"(_d) : "r"(_m), "r"(_p) : "memory"); \
    if (!_d) { \
        asm volatile("{\n\t.reg .pred P1;\n\tWL_%=:\n\t" \
            "mbarrier.try_wait.parity.acquire.cta.shared::cta.b64 P1, [%0], %1, 0x989680;\n\t" \
            "@P1 bra.uni WD_%=;\n\tbra.uni WL_%=;\n\tWD_%=:\n\t}" \
            :: "r"(_m), "r"(_p) : "memory"); \
    } } while (0)
#define FENCE_PROXY_ASYNC() asm volatile("fence.proxy.async.shared::cta;" ::: "memory")

__device__ __forceinline__ void tma_ld_2d(uint32_t dst, const CUtensorMap* map,
                                          int cx, int cy, uint32_t mbar) {
    asm volatile(
        "cp.async.bulk.tensor.2d.shared::cta.global.tile.mbarrier::complete_tx::bytes "
        "[%0], [%1, {%2, %3}], [%4];"
        :: "r"(dst), "l"(map), "r"(cx), "r"(cy), "r"(mbar) : "memory");
}
__device__ __forceinline__ void ldsm4(uint32_t r[4], uint32_t addr) {
    asm volatile("ldmatrix.sync.aligned.m8n8.x4.shared.b16 {%0,%1,%2,%3}, [%4];"
        : "=r"(r[0]), "=r"(r[1]), "=r"(r[2]), "=r"(r[3]) : "r"(addr));
}
__device__ __forceinline__ void mma_bf16(float d[4], const uint32_t a[4], const uint32_t b[2]) {
    asm volatile("mma.sync.aligned.m16n8k16.row.col.f32.bf16.bf16.f32 "
        "{%0,%1,%2,%3}, {%4,%5,%6,%7}, {%8,%9}, {%0,%1,%2,%3};"
        : "+f"(d[0]), "+f"(d[1]), "+f"(d[2]), "+f"(d[3])
        : "r"(a[0]), "r"(a[1]), "r"(a[2]), "r"(a[3]), "r"(b[0]), "r"(b[1]));
}

// monotone float<->uint encoding for atomicMax over signed floats
__device__ __forceinline__ unsigned int encf(float f) {
    unsigned int u = __float_as_uint(f);
    return (u & 0x80000000u) ? ~u : (u | 0x80000000u);
}
__device__ __forceinline__ float decf(unsigned int e) {
    unsigned int u = (e & 0x80000000u) ? (e & 0x7fffffffu) : ~e;
    return __uint_as_float(u);
}

// ---- kernel 1: warp-per-row init + L2-normalize + RNE bf16 convert ----------
#define ROWS_TOTAL  (M_ + N_)          // 48240
#define PREP_BLOCKS (ROWS_TOTAL / 8)   // 6030 (8 warps/block, exact)
#define MV_PER_BLK  ((M_*G_ + PREP_BLOCKS - 1) / PREP_BLOCKS)   // 48
__global__ __launch_bounds__(256)
void prep_kernel(const float* __restrict__ audio,
                 const float* __restrict__ visual) {
    const int tid  = threadIdx.x;
    const int lane = tid & 31;
    const int w    = tid >> 5;
    const int blk  = blockIdx.x;

    // init slice of g_maxvis
    {
        int base = blk * MV_PER_BLK;
        for (int j = tid; j < MV_PER_BLK; j += 256) {
            int i = base + j;
            if (i < M_ * G_) g_maxvis[i] = 0u;
        }
        if (blk == 0 && tid == 0) g_fraccnt = 0;
    }

    const int grow = blk * 8 + w;      // 0..48239
    const int which = (grow >= M_);
    const float* in = which ? visual : audio;
    __nv_bfloat16* out = which ? g_V : g_A;
    const size_t row = which ? (size_t)(grow - M_) : (size_t)grow;

    // each lane: 4 float4 (16 floats), coalesced
    float4 v[4];
    float s = 0.f;
    const float4* ip = reinterpret_cast<const float4*>(in + row * D_);
#pragma unroll
    for (int k = 0; k < 4; k++) {
        v[k] = ip[lane + k * 32];
        s += v[k].x * v[k].x + v[k].y * v[k].y + v[k].z * v[k].z + v[k].w * v[k].w;
    }
#pragma unroll
    for (int o = 16; o; o >>= 1) s += __shfl_xor_sync(0xffffffffu, s, o);
    const float iv = 1.0f / fmaxf(sqrtf(s), 1e-12f);

    uint2* op = reinterpret_cast<uint2*>(out + row * D_);
#pragma unroll
    for (int k = 0; k < 4; k++) {
        __nv_bfloat162 h01 = __float22bfloat162_rn(make_float2(v[k].x * iv, v[k].y * iv));
        __nv_bfloat162 h23 = __float22bfloat162_rn(make_float2(v[k].z * iv, v[k].w * iv));
        uint2 hu;
        hu.x = *reinterpret_cast<uint32_t*>(&h01);
        hu.y = *reinterpret_cast<uint32_t*>(&h23);
        op[lane + k * 32] = hu;
    }
}

// ------- kernel 2: persistent bf16 GEMM (round-14 exact) ---------------------
__global__ __launch_bounds__(416, 1)
void gemm_mma(const __grid_constant__ CUtensorMap tmA,
              const __grid_constant__ CUtensorMap tmV,
              const float* __restrict__ tempP) {
    extern __shared__ __align__(1024) char dsmem[];
    __shared__ uint64_t s_full[NSTAGE], s_empty[NSTAGE];

    const int tid   = threadIdx.x;
    const int lane  = tid & 31;
    const int wid   = tid >> 5;
    const uint32_t sbase = smem_u32(dsmem);
    uint32_t FULL[NSTAGE], EMPTY[NSTAGE];
#pragma unroll
    for (int i = 0; i < NSTAGE; i++) {
        FULL[i]  = smem_u32(&s_full[i]);
        EMPTY[i] = smem_u32(&s_empty[i]);
    }

    if (tid == 0) {
#pragma unroll
        for (int i = 0; i < NSTAGE; i++) {
            MBARRIER_INIT(FULL[i], 1);
            MBARRIER_INIT(EMPTY[i], NCW);
        }
        FENCE_PROXY_ASYNC();
    }
    __syncthreads();

    const int bx = blockIdx.x;
    const int ntiles = (bx < NTILES) ? ((NTILES - 1 - bx) / GRID_ + 1) : 0;
    const int totChunks = ntiles * KCH;

    // ================= producer warp (single thread) =================
    if (tid == 384) {
        for (int gc = 0; gc < totChunks; gc++) {
            const int st = gc % NSTAGE;
            const int n  = gc / NSTAGE;
            if (n >= 1) MBARRIER_WAIT_PARITY(EMPTY[st], (n - 1) & 1);
            const int s   = bx + (gc / KCH) * GRID_;
            const int c   = gc % KCH;
            const int rm0 = (s % NTM) * 128;
            const int cn0 = (s / NTM) * BN_;
            const int k0  = c * 64;
            const uint32_t stg = sbase + st * STAGE_BYTES;
            MBARRIER_EXPECT_TX(FULL[st], STAGE_BYTES);
            tma_ld_2d(stg,           &tmA, k0, rm0, FULL[st]);
            tma_ld_2d(stg + A_BYTES, &tmV, k0, cn0, FULL[st]);
        }
        return;
    }
    if (tid > 384) return;

    // ================= consumer warps (0..11) =================
    const int warpM = wid & 3;        // 4 row groups of 32
    const int warpN = wid >> 2;       // 3 col groups of 64
    const float invT = 1.0f / __ldg(tempP);

    const uint32_t laneHi = (lane & 16);
    uint32_t offA[2][4], offB[4][4];
#pragma unroll
    for (int mt = 0; mt < 2; mt++) {
        int r = warpM * 32 + mt * 16 + (lane & 15);
        uint32_t sw = (r & 7) << 4;
#pragma unroll
        for (int ks = 0; ks < 4; ks++)
            offA[mt][ks] = (uint32_t)(r * 128) + ((ks * 32 + laneHi) ^ sw);
    }
#pragma unroll
    for (int p = 0; p < 4; p++) {
        int r = warpN * 64 + p * 16 + (lane & 15);
        uint32_t sw = (r & 7) << 4;
#pragma unroll
        for (int ks = 0; ks < 4; ks++)
            offB[p][ks] = (uint32_t)(r * 128) + ((ks * 32 + laneHi) ^ sw);
    }

    int gc = 0;
    for (int s = bx; s < NTILES; s += GRID_) {
        const int rm0 = (s % NTM) * 128;
        const int cn0 = (s / NTM) * BN_;

        float acc[2][8][4];
#pragma unroll
        for (int mt = 0; mt < 2; mt++)
#pragma unroll
            for (int nt = 0; nt < 8; nt++)
#pragma unroll
                for (int e = 0; e < 4; e++) acc[mt][nt][e] = 0.f;

        for (int c = 0; c < KCH; c++, gc++) {
            const int st = gc % NSTAGE;
            MBARRIER_WAIT_PARITY(FULL[st], (gc / NSTAGE) & 1);
            const uint32_t pA = sbase + st * STAGE_BYTES;
            const uint32_t pV = pA + A_BYTES;

#pragma unroll
            for (int ks = 0; ks < 4; ks++) {       // 4 k16 steps per k64 chunk
                uint32_t a[2][4];
                ldsm4(a[0], pA + offA[0][ks]);
                ldsm4(a[1], pA + offA[1][ks]);
                uint32_t bfr[8][2];
#pragma unroll
                for (int p = 0; p < 4; p++) {
                    uint32_t t[4];
                    ldsm4(t, pV + offB[p][ks]);
                    bfr[2*p][0]   = t[0]; bfr[2*p][1]   = t[2];
                    bfr[2*p+1][0] = t[1]; bfr[2*p+1][1] = t[3];
                }
#pragma unroll
                for (int mt = 0; mt < 2; mt++)
#pragma unroll
                    for (int nt = 0; nt < 8; nt++)
                        mma_bf16(acc[mt][nt], a[mt], bfr[nt]);
            }
            if (lane == 0) MBARRIER_ARRIVE(EMPTY[st]);
        }

        // ---- fused epilogue: x invT, segmented max, clamp^2 sum --------------
        const int gB  = cn0 / NV_;
        const int bnd = (gB + 1) * NV_;
        float ssq = 0.f;
#pragma unroll
        for (int mt = 0; mt < 2; mt++) {
            const int row0 = rm0 + warpM * 32 + mt * 16 + (lane >> 2);
            const int row1 = row0 + 8;
            float mx[2][2] = {{-3.0e38f, -3.0e38f}, {-3.0e38f, -3.0e38f}};
#pragma unroll
            for (int nt = 0; nt < 8; nt++) {
                const int c0 = cn0 + warpN * 64 + nt * 8 + (lane & 3) * 2;
#pragma unroll
                for (int e = 0; e < 4; e++) {
                    const int row = (e < 2) ? row0 : row1;
                    float sv = acc[mt][nt][e] * invT;
                    float nn = fmaxf(fminf(sv, 0.f), -20.f);
                    ssq += nn * nn;          // OOB rows: acc==0 (TMA zero-fill) -> 0
                    if (row < M_) {
                        int g = ((c0 + (e & 1)) < bnd) ? 0 : 1;
                        mx[e >> 1][g] = fmaxf(mx[e >> 1][g], sv);
                    }
                }
            }
#pragma unroll
            for (int h = 0; h < 2; h++)
#pragma unroll
                for (int g = 0; g < 2; g++) {
                    float v = mx[h][g];
                    v = fmaxf(v, __shfl_xor_sync(0xffffffffu, v, 1));
                    v = fmaxf(v, __shfl_xor_sync(0xffffffffu, v, 2));
                    mx[h][g] = v;
                }
            if ((lane & 3) == 0) {
                if (row0 < M_) {
                    if (mx[0][0] > -1.0e38f) atomicMax(&g_maxvis[row0 * G_ + gB],     encf(mx[0][0]));
                    if (mx[0][1] > -1.0e38f) atomicMax(&g_maxvis[row0 * G_ + gB + 1], encf(mx[0][1]));
                }
                if (row1 < M_) {
                    if (mx[1][0] > -1.0e38f) atomicMax(&g_maxvis[row1 * G_ + gB],     encf(mx[1][0]));
                    if (mx[1][1] > -1.0e38f) atomicMax(&g_maxvis[row1 * G_ + gB + 1], encf(mx[1][1]));
                }
            }
        }
#pragma unroll
        for (int o = 16; o; o >>= 1) ssq += __shfl_xor_sync(0xffffffffu, ssq, o);
        if (lane == 0) g_sumsq[s * NCW + wid] = ssq;   // per-warp partial
    }
}

// ---------------- kernel 3: temporal aggregation (round-14 exact) ------------
__global__ void stage2(const float* __restrict__ sfP, const float* __restrict__ thP) {
    const int p = blockIdx.x;
    const int x = p / B_;
    const int y = p % B_;
    const int a = threadIdx.x;

    const float th = 1.0f / (1.0f + expf(-__ldg(thP)));
    const float sf = __ldg(sfP);

    float token = 0.f, sr = 0.f;
    int cnt = 0;
    if (a < NA_) {
        float wsum = 0.f, ws = 0.f;
        const int base = (x * NA_ + a) * G_ + y * T_;
#pragma unroll
        for (int t = 0; t < T_; t++) {
            float m = decf(g_maxvis[base + t]);
            float raw = m - th;
            float sel = fmaxf(raw, 0.f) * sf;
            ws += m * sel;
            wsum += sel;
            cnt += (raw > 0.f) ? 1 : 0;
            if (x == y) sr += 0.5f * (tanhf(20.f * raw) + 1.f);
        }
        token = ws / fmaxf(wsum, 1e-6f);
    }
    __shared__ float st[64], ss[64];
    __shared__ int sc[64];
    st[threadIdx.x] = token; ss[threadIdx.x] = sr; sc[threadIdx.x] = cnt;
    __syncthreads();
    if (threadIdx.x == 0) {
        float ts = 0.f, srs = 0.f; int c = 0;
        for (int i = 0; i < 64; i++) { ts += st[i]; srs += ss[i]; c += sc[i]; }
        g_clip[x * B_ + y] = ts / (float)NA_;
        atomicAdd(&g_fraccnt, c);
        if (x == y) g_selsum[x] = srs;
    }
}

// ---------------- kernel 4: finalize 5 scalars (round-14 exact) --------------
__global__ __launch_bounds__(1024)
void stage3(float* __restrict__ out,
            const float* __restrict__ tempP,
            const float* __restrict__ sfP,
            const float* __restrict__ thP) {
    const int t = threadIdx.x;
    __shared__ float la[B_], lv[B_];
    __shared__ float sp[1024];

    if (t < B_) {
        float m = -3.0e38f;
        for (int j = 0; j < B_; j++) m = fmaxf(m, g_clip[t * B_ + j]);
        float s = 0.f;
        for (int j = 0; j < B_; j++) s += expf(g_clip[t * B_ + j] - m);
        la[t] = -(g_clip[t * B_ + t] - (logf(s) + m));
        float m2 = -3.0e38f;
        for (int j = 0; j < B_; j++) m2 = fmaxf(m2, g_clip[j * B_ + t]);
        float s2 = 0.f;
        for (int j = 0; j < B_; j++) s2 += expf(g_clip[j * B_ + t] - m2);
        lv[t] = -(g_clip[t * B_ + t] - (logf(s2) + m2));
    }
    float acc = 0.f;
    for (int i = t; i < NSUMSQ; i += 1024) acc += g_sumsq[i];
    sp[t] = acc;
    __syncthreads();
#pragma unroll
    for (int o = 512; o; o >>= 1) {
        if (t < o) sp[t] += sp[t + o];
        __syncthreads();
    }

    if (t == 0) {
        float sumsq = sp[0];

        float contr = 0.f;
        for (int i = 0; i < B_; i++) contr += la[i] + lv[i];
        contr = contr / (float)B_ * 0.5f;

        float temp = *tempP, sf = *sfP;
        float th = 1.0f / (1.0f + expf(-(*thP)));

        float l_nonneg = sumsq / 56448000.0f;
        float lt = logf(temp);
        float tlow = fmaxf(-lt, 0.f);  tlow *= tlow;
        float thigh = fmaxf(lt - logf(4.0f), 0.f); thigh *= thigh;
        float l_cal = tlow + thigh;
        float a1 = fmaxf(th - 0.9f, 0.f), a2 = fmaxf(0.1f - th, 0.f);
        float l_th = a1 * a1 + a2 * a2;
        float b1 = fmaxf(sf - 20.f, 0.f), b2 = fmaxf(1.f - sf, 0.f);
        float l_sc = b1 * b1 + b2 * b2;
        float reg = 0.15f * l_nonneg + 2.0f * l_cal + 0.1f * l_th + 0.1f * l_sc;

        float frac = (float)g_fraccnt / 288000.0f;

        float selmean = 0.f;
        for (int i = 0; i < B_; i++) selmean += g_selsum[i];
        selmean /= 12000.0f;
        float selrew = -0.1f * log1pf(selmean);

        out[0] = selrew + contr + reg;
        out[1] = contr;
        out[2] = reg;
        out[3] = frac;
        out[4] = selrew;
    }
}

// ---------------- host: tensor maps via driver entry point ----------------
typedef CUresult (*EncTiledFn)(CUtensorMap*, CUtensorMapDataType, cuuint32_t, void*,
                               const cuuint64_t*, const cuuint64_t*, const cuuint32_t*,
                               const cuuint32_t*, CUtensorMapInterleave, CUtensorMapSwizzle,
                               CUtensorMapL2promotion, CUtensorMapFloatOOBfill);

static void make_map(EncTiledFn enc, CUtensorMap* m, void* base,
                     unsigned long long rows, unsigned box1) {
    cuuint64_t dims[2]    = {(cuuint64_t)D_, (cuuint64_t)rows};
    cuuint64_t strides[1] = {(cuuint64_t)(D_ * 2)};
    cuuint32_t box[2]     = {64u, box1};     // 64 bf16 = 128B rows (SW128 atom)
    cuuint32_t es[2]      = {1u, 1u};
    enc(m, CU_TENSOR_MAP_DATA_TYPE_BFLOAT16, 2, base, dims, strides, box, es,
        CU_TENSOR_MAP_INTERLEAVE_NONE, CU_TENSOR_MAP_SWIZZLE_128B,
        CU_TENSOR_MAP_L2_PROMOTION_L2_128B, CU_TENSOR_MAP_FLOAT_OOB_FILL_NONE);
}

extern "C" void kernel_launch(void* const* d_in, const int* in_sizes, int n_in,
                              void* d_out, int out_size) {
    const float* audio  = (const float*)d_in[0];
    const float* visual = (const float*)d_in[1];
    const float* tempP  = (const float*)d_in[2];
    const float* sfP    = (const float*)d_in[3];
    const float* thP    = (const float*)d_in[4];
    float* out = (float*)d_out;

    void* encPtr = nullptr;
    cudaDriverEntryPointQueryResult qres;
    cudaGetDriverEntryPoint("cuTensorMapEncodeTiled", &encPtr, cudaEnableDefault, &qres);
    EncTiledFn enc = (EncTiledFn)encPtr;

    void *pA, *pV;
    cudaGetSymbolAddress(&pA, g_A);
    cudaGetSymbolAddress(&pV, g_V);

    CUtensorMap tmA, tmV;
    make_map(enc, &tmA, pA, M_, 128u);
    make_map(enc, &tmV, pV, N_, 192u);

    cudaFuncSetAttribute(gemm_mma, cudaFuncAttributeMaxDynamicSharedMemorySize, SMEM_TOTAL);

    prep_kernel<<<PREP_BLOCKS, 256>>>(audio, visual);
    gemm_mma<<<GRID_, 416, SMEM_TOTAL>>>(tmA, tmV, tempP);
    stage2<<<B_ * B_, 64>>>(sfP, thP);
    stage3<<<1, 1024>>>(out, tempP, sfP, thP);
}